// round 1
// baseline (speedup 1.0000x reference)
#include <cuda_runtime.h>
#include <stdint.h>

// RGINConv: out = feat + segment_sum_dst( feat[src] @ W[etype] )
//
// Plan:
//   1. Y[r] = feat @ W[r]  (8 GEMMs, tf32 mma.sync, fp32 accum) -> g_Y scratch
//   2. Build CSR of edges grouped by dst (histogram + scan + scatter)
//   3. Pull: warp per node, acc = feat[n] + sum of Y rows of incoming edges
//
// All scratch is __device__ global (no allocations). All kernels on the
// default stream -> sequentially ordered, graph-capturable.

#define DFEAT 128
#define MAX_N 50048
#define MAX_E 640000
#define MAX_R 8

__device__ float    g_Y[(size_t)MAX_R * MAX_N * DFEAT];  // ~205 MB scratch
__device__ int      g_rowptr[MAX_N + 1];
__device__ int      g_cursor[MAX_N];
__device__ int      g_deg[MAX_N];
__device__ unsigned g_elist[MAX_E];   // element offset into g_Y per edge

// ---------------------------------------------------------------------------
// GEMM: Y[rel] = feat @ W[rel],  M = n_nodes, N = K = 128, tf32 tensor cores.
// CTA tile: 64(M) x 128(N); 8 warps in 2(M) x 4(N) grid, warp tile 32x32.
// ---------------------------------------------------------------------------
#define TM 64
#define AS_LD 132   // padded A smem row stride (words)
#define BS_LD 136   // padded B smem row stride (words)

__global__ void __launch_bounds__(256, 2)
gemm_feat_w(const float* __restrict__ feat, const float* __restrict__ W, int n_nodes)
{
    extern __shared__ unsigned sh[];
    unsigned* As = sh;                    // [TM][AS_LD]
    unsigned* Bs = sh + TM * AS_LD;       // [128][BS_LD]

    const int rel  = blockIdx.y;
    const int row0 = blockIdx.x * TM;
    const int tid  = threadIdx.x;

    // Load A tile (TM x 128 floats), convert to tf32 in smem. 8 float4/thread.
#pragma unroll
    for (int it = 0; it < (TM * DFEAT) / (256 * 4); ++it) {
        int idx = it * 256 + tid;           // float4 index
        int r   = idx >> 5;                 // 32 float4 per row
        int c   = (idx & 31) * 4;
        float4 v = make_float4(0.f, 0.f, 0.f, 0.f);
        int gr = row0 + r;
        if (gr < n_nodes) v = *(const float4*)(feat + (size_t)gr * DFEAT + c);
        unsigned* p = As + r * AS_LD + c;
        asm("cvt.rna.tf32.f32 %0, %1;" : "=r"(p[0]) : "f"(v.x));
        asm("cvt.rna.tf32.f32 %0, %1;" : "=r"(p[1]) : "f"(v.y));
        asm("cvt.rna.tf32.f32 %0, %1;" : "=r"(p[2]) : "f"(v.z));
        asm("cvt.rna.tf32.f32 %0, %1;" : "=r"(p[3]) : "f"(v.w));
    }
    // Load B tile = W[rel] (128 x 128), tf32 in smem. 16 float4/thread.
    const float* Wr = W + (size_t)rel * DFEAT * DFEAT;
#pragma unroll
    for (int it = 0; it < (DFEAT * DFEAT) / (256 * 4); ++it) {
        int idx = it * 256 + tid;
        int r   = idx >> 5;
        int c   = (idx & 31) * 4;
        float4 v = *(const float4*)(Wr + r * DFEAT + c);
        unsigned* p = Bs + r * BS_LD + c;
        asm("cvt.rna.tf32.f32 %0, %1;" : "=r"(p[0]) : "f"(v.x));
        asm("cvt.rna.tf32.f32 %0, %1;" : "=r"(p[1]) : "f"(v.y));
        asm("cvt.rna.tf32.f32 %0, %1;" : "=r"(p[2]) : "f"(v.z));
        asm("cvt.rna.tf32.f32 %0, %1;" : "=r"(p[3]) : "f"(v.w));
    }
    __syncthreads();

    const int wid  = tid >> 5;
    const int lane = tid & 31;
    const int g    = lane >> 2;   // group id 0..7
    const int c    = lane & 3;    // thread in group 0..3
    const int wm   = wid & 1;     // warp M index (rows wm*32)
    const int wn   = wid >> 1;    // warp N index (cols wn*32)

    float acc[2][4][4];
#pragma unroll
    for (int mt = 0; mt < 2; ++mt)
#pragma unroll
        for (int nt = 0; nt < 4; ++nt)
#pragma unroll
            for (int i = 0; i < 4; ++i) acc[mt][nt][i] = 0.f;

#pragma unroll
    for (int k0 = 0; k0 < DFEAT; k0 += 8) {
        unsigned a[2][4], b[4][2];
#pragma unroll
        for (int mt = 0; mt < 2; ++mt) {
            int rb = wm * 32 + mt * 16;
            a[mt][0] = As[(rb + g)     * AS_LD + k0 + c];
            a[mt][1] = As[(rb + g + 8) * AS_LD + k0 + c];
            a[mt][2] = As[(rb + g)     * AS_LD + k0 + c + 4];
            a[mt][3] = As[(rb + g + 8) * AS_LD + k0 + c + 4];
        }
#pragma unroll
        for (int nt = 0; nt < 4; ++nt) {
            int nb = wn * 32 + nt * 8;
            b[nt][0] = Bs[(k0 + c)     * BS_LD + nb + g];
            b[nt][1] = Bs[(k0 + c + 4) * BS_LD + nb + g];
        }
#pragma unroll
        for (int mt = 0; mt < 2; ++mt)
#pragma unroll
            for (int nt = 0; nt < 4; ++nt)
                asm volatile(
                    "mma.sync.aligned.m16n8k8.row.col.f32.tf32.tf32.f32 "
                    "{%0,%1,%2,%3}, {%4,%5,%6,%7}, {%8,%9}, {%0,%1,%2,%3};"
                    : "+f"(acc[mt][nt][0]), "+f"(acc[mt][nt][1]),
                      "+f"(acc[mt][nt][2]), "+f"(acc[mt][nt][3])
                    : "r"(a[mt][0]), "r"(a[mt][1]), "r"(a[mt][2]), "r"(a[mt][3]),
                      "r"(b[nt][0]), "r"(b[nt][1]));
    }

    // Store D. c0,c1 at (row g, cols 2c,2c+1); c2,c3 at row g+8.
    float* Yr = g_Y + (size_t)rel * n_nodes * DFEAT;
#pragma unroll
    for (int mt = 0; mt < 2; ++mt) {
        int r_lo = row0 + wm * 32 + mt * 16 + g;
        int r_hi = r_lo + 8;
#pragma unroll
        for (int nt = 0; nt < 4; ++nt) {
            int col = wn * 32 + nt * 8 + 2 * c;
            if (r_lo < n_nodes)
                *(float2*)(Yr + (size_t)r_lo * DFEAT + col) =
                    make_float2(acc[mt][nt][0], acc[mt][nt][1]);
            if (r_hi < n_nodes)
                *(float2*)(Yr + (size_t)r_hi * DFEAT + col) =
                    make_float2(acc[mt][nt][2], acc[mt][nt][3]);
        }
    }
}

// ---------------------------------------------------------------------------
// CSR build
// ---------------------------------------------------------------------------
__global__ void zero_deg_k(int n)
{
    int i = blockIdx.x * blockDim.x + threadIdx.x;
    if (i < n) g_deg[i] = 0;
}

__global__ void hist_k(const int* __restrict__ dst, int E)
{
    int e = blockIdx.x * blockDim.x + threadIdx.x;
    if (e < E) atomicAdd(&g_deg[dst[e]], 1);
}

// Single-CTA exclusive scan: each thread owns a contiguous chunk.
__global__ void scan_k(int n, int E)
{
    const int tid = threadIdx.x;
    const int CH  = (n + 1023) >> 10;
    const int base = tid * CH;

    int sum = 0;
    for (int j = 0; j < CH; ++j) {
        int idx = base + j;
        if (idx < n) sum += g_deg[idx];
    }
    // block exclusive scan of per-thread sums
    const int lane = tid & 31, wid = tid >> 5;
    int v = sum;
#pragma unroll
    for (int off = 1; off < 32; off <<= 1) {
        int t = __shfl_up_sync(0xffffffffu, v, off);
        if (lane >= off) v += t;
    }
    __shared__ int ws[32];
    if (lane == 31) ws[wid] = v;
    __syncthreads();
    if (wid == 0) {
        int w = ws[lane];
#pragma unroll
        for (int off = 1; off < 32; off <<= 1) {
            int t = __shfl_up_sync(0xffffffffu, w, off);
            if (lane >= off) w += t;
        }
        ws[lane] = w;
    }
    __syncthreads();
    int excl = v - sum + (wid ? ws[wid - 1] : 0);

    int run = excl;
    for (int j = 0; j < CH; ++j) {
        int idx = base + j;
        if (idx < n) {
            g_rowptr[idx] = run;
            g_cursor[idx] = run;
            run += g_deg[idx];
        }
    }
    if (tid == 0) g_rowptr[n] = E;
}

__global__ void scatter_k(const int* __restrict__ src, const int* __restrict__ dst,
                          const int* __restrict__ et, int E, int n)
{
    int e = blockIdx.x * blockDim.x + threadIdx.x;
    if (e >= E) return;
    int d   = dst[e];
    int pos = atomicAdd(&g_cursor[d], 1);
    g_elist[pos] = ((unsigned)et[e] * (unsigned)n + (unsigned)src[e]) * (unsigned)DFEAT;
}

// ---------------------------------------------------------------------------
// Pull: one warp per node. acc = feat[n] + sum over incoming edges of Y row.
// ---------------------------------------------------------------------------
__global__ void __launch_bounds__(256)
pull_k(const float* __restrict__ feat, float* __restrict__ out, int n)
{
    int gw   = (blockIdx.x * 256 + threadIdx.x) >> 5;
    int lane = threadIdx.x & 31;
    if (gw >= n) return;

    int s = g_rowptr[gw];
    int e = g_rowptr[gw + 1];

    float4 acc = *((const float4*)feat + (size_t)gw * 32 + lane);

    int i = s;
    for (; i + 2 <= e; i += 2) {
        unsigned o0 = g_elist[i];
        unsigned o1 = g_elist[i + 1];
        float4 v0 = *(const float4*)(g_Y + (size_t)o0 + lane * 4);
        float4 v1 = *(const float4*)(g_Y + (size_t)o1 + lane * 4);
        acc.x += v0.x; acc.y += v0.y; acc.z += v0.z; acc.w += v0.w;
        acc.x += v1.x; acc.y += v1.y; acc.z += v1.z; acc.w += v1.w;
    }
    if (i < e) {
        unsigned o = g_elist[i];
        float4 v = *(const float4*)(g_Y + (size_t)o + lane * 4);
        acc.x += v.x; acc.y += v.y; acc.z += v.z; acc.w += v.w;
    }

    *((float4*)out + (size_t)gw * 32 + lane) = acc;
}

// ---------------------------------------------------------------------------
// Launch
// ---------------------------------------------------------------------------
extern "C" void kernel_launch(void* const* d_in, const int* in_sizes, int n_in,
                              void* d_out, int out_size)
{
    const float* feat = (const float*)d_in[0];
    const float* W    = (const float*)d_in[1];
    const int*   et   = (const int*)d_in[2];
    const int*   src  = (const int*)d_in[3];
    const int*   dst  = (const int*)d_in[4];
    float*       out  = (float*)d_out;

    const int n = in_sizes[0] / DFEAT;                 // 50000
    const int R = in_sizes[1] / (DFEAT * DFEAT);       // 8
    const int E = in_sizes[2];                          // 640000

    const int smem_bytes = (TM * AS_LD + DFEAT * BS_LD) * 4;  // ~103 KB
    cudaFuncSetAttribute(gemm_feat_w,
                         cudaFuncAttributeMaxDynamicSharedMemorySize, smem_bytes);

    dim3 gg((n + TM - 1) / TM, R);
    gemm_feat_w<<<gg, 256, smem_bytes>>>(feat, W, n);

    zero_deg_k<<<(n + 255) / 256, 256>>>(n);
    hist_k<<<(E + 255) / 256, 256>>>(dst, E);
    scan_k<<<1, 1024>>>(n, E);
    scatter_k<<<(E + 255) / 256, 256>>>(src, dst, et, E, n);

    pull_k<<<(n * 32 + 255) / 256, 256>>>(feat, out, n);
}

// round 5
// speedup vs baseline: 1.3492x; 1.3492x over previous
#include <cuda_runtime.h>
#include <stdint.h>

// RGINConv: out = feat + segment_sum_dst( feat[src] @ W[etype] )
//
//   1. Y[r] = feat @ W[r]  (8 GEMMs, tf32 mma.sync, fp32 accum) -> g_Y scratch
//   2. Build CSR of edges grouped by dst (histogram + 3-kernel parallel scan
//      + scatter)  [scan was 77us single-CTA; now hierarchical, ~8us]
//   3. Pull: warp per node, acc = feat[n] + sum of Y rows of incoming edges

#define DFEAT 128
#define MAX_N 50048
#define MAX_E 640000
#define MAX_R 8
#define SCAN_CHUNK 1024
#define MAX_NB ((MAX_N + SCAN_CHUNK - 1) / SCAN_CHUNK)

__device__ float    g_Y[(size_t)MAX_R * MAX_N * DFEAT];  // ~205 MB scratch
__device__ int      g_rowptr[MAX_N + 1];
__device__ int      g_cursor[MAX_N];
__device__ int      g_deg[MAX_N];
__device__ int      g_bsum[MAX_NB];
__device__ unsigned g_elist[MAX_E];   // element offset into g_Y per edge

// ---------------------------------------------------------------------------
// GEMM: Y[rel] = feat @ W[rel],  M = n_nodes, N = K = 128, tf32 tensor cores.
// CTA tile: 64(M) x 128(N); 8 warps in 2(M) x 4(N) grid, warp tile 32x32.
// ---------------------------------------------------------------------------
#define TM 64
#define AS_LD 132   // padded A smem row stride (words)
#define BS_LD 136   // padded B smem row stride (words)

__global__ void __launch_bounds__(256, 2)
gemm_feat_w(const float* __restrict__ feat, const float* __restrict__ W, int n_nodes)
{
    extern __shared__ unsigned sh[];
    unsigned* As = sh;                    // [TM][AS_LD]
    unsigned* Bs = sh + TM * AS_LD;       // [128][BS_LD]

    const int rel  = blockIdx.y;
    const int row0 = blockIdx.x * TM;
    const int tid  = threadIdx.x;

#pragma unroll
    for (int it = 0; it < (TM * DFEAT) / (256 * 4); ++it) {
        int idx = it * 256 + tid;           // float4 index
        int r   = idx >> 5;                 // 32 float4 per row
        int c   = (idx & 31) * 4;
        float4 v = make_float4(0.f, 0.f, 0.f, 0.f);
        int gr = row0 + r;
        if (gr < n_nodes) v = *(const float4*)(feat + (size_t)gr * DFEAT + c);
        unsigned* p = As + r * AS_LD + c;
        asm("cvt.rna.tf32.f32 %0, %1;" : "=r"(p[0]) : "f"(v.x));
        asm("cvt.rna.tf32.f32 %0, %1;" : "=r"(p[1]) : "f"(v.y));
        asm("cvt.rna.tf32.f32 %0, %1;" : "=r"(p[2]) : "f"(v.z));
        asm("cvt.rna.tf32.f32 %0, %1;" : "=r"(p[3]) : "f"(v.w));
    }
    const float* Wr = W + (size_t)rel * DFEAT * DFEAT;
#pragma unroll
    for (int it = 0; it < (DFEAT * DFEAT) / (256 * 4); ++it) {
        int idx = it * 256 + tid;
        int r   = idx >> 5;
        int c   = (idx & 31) * 4;
        float4 v = *(const float4*)(Wr + r * DFEAT + c);
        unsigned* p = Bs + r * BS_LD + c;
        asm("cvt.rna.tf32.f32 %0, %1;" : "=r"(p[0]) : "f"(v.x));
        asm("cvt.rna.tf32.f32 %0, %1;" : "=r"(p[1]) : "f"(v.y));
        asm("cvt.rna.tf32.f32 %0, %1;" : "=r"(p[2]) : "f"(v.z));
        asm("cvt.rna.tf32.f32 %0, %1;" : "=r"(p[3]) : "f"(v.w));
    }
    __syncthreads();

    const int wid  = tid >> 5;
    const int lane = tid & 31;
    const int g    = lane >> 2;   // group id 0..7
    const int c    = lane & 3;    // thread in group 0..3
    const int wm   = wid & 1;     // warp M index (rows wm*32)
    const int wn   = wid >> 1;    // warp N index (cols wn*32)

    float acc[2][4][4];
#pragma unroll
    for (int mt = 0; mt < 2; ++mt)
#pragma unroll
        for (int nt = 0; nt < 4; ++nt)
#pragma unroll
            for (int i = 0; i < 4; ++i) acc[mt][nt][i] = 0.f;

#pragma unroll
    for (int k0 = 0; k0 < DFEAT; k0 += 8) {
        unsigned a[2][4], b[4][2];
#pragma unroll
        for (int mt = 0; mt < 2; ++mt) {
            int rb = wm * 32 + mt * 16;
            a[mt][0] = As[(rb + g)     * AS_LD + k0 + c];
            a[mt][1] = As[(rb + g + 8) * AS_LD + k0 + c];
            a[mt][2] = As[(rb + g)     * AS_LD + k0 + c + 4];
            a[mt][3] = As[(rb + g + 8) * AS_LD + k0 + c + 4];
        }
#pragma unroll
        for (int nt = 0; nt < 4; ++nt) {
            int nb = wn * 32 + nt * 8;
            b[nt][0] = Bs[(k0 + c)     * BS_LD + nb + g];
            b[nt][1] = Bs[(k0 + c + 4) * BS_LD + nb + g];
        }
#pragma unroll
        for (int mt = 0; mt < 2; ++mt)
#pragma unroll
            for (int nt = 0; nt < 4; ++nt)
                asm volatile(
                    "mma.sync.aligned.m16n8k8.row.col.f32.tf32.tf32.f32 "
                    "{%0,%1,%2,%3}, {%4,%5,%6,%7}, {%8,%9}, {%0,%1,%2,%3};"
                    : "+f"(acc[mt][nt][0]), "+f"(acc[mt][nt][1]),
                      "+f"(acc[mt][nt][2]), "+f"(acc[mt][nt][3])
                    : "r"(a[mt][0]), "r"(a[mt][1]), "r"(a[mt][2]), "r"(a[mt][3]),
                      "r"(b[nt][0]), "r"(b[nt][1]));
    }

    float* Yr = g_Y + (size_t)rel * n_nodes * DFEAT;
#pragma unroll
    for (int mt = 0; mt < 2; ++mt) {
        int r_lo = row0 + wm * 32 + mt * 16 + g;
        int r_hi = r_lo + 8;
#pragma unroll
        for (int nt = 0; nt < 4; ++nt) {
            int col = wn * 32 + nt * 8 + 2 * c;
            if (r_lo < n_nodes)
                *(float2*)(Yr + (size_t)r_lo * DFEAT + col) =
                    make_float2(acc[mt][nt][0], acc[mt][nt][1]);
            if (r_hi < n_nodes)
                *(float2*)(Yr + (size_t)r_hi * DFEAT + col) =
                    make_float2(acc[mt][nt][2], acc[mt][nt][3]);
        }
    }
}

// ---------------------------------------------------------------------------
// CSR build
// ---------------------------------------------------------------------------
__global__ void zero_deg_k(int n)
{
    int i = blockIdx.x * blockDim.x + threadIdx.x;
    if (i < n) g_deg[i] = 0;
}

__global__ void hist_k(const int* __restrict__ dst, int E)
{
    int e = blockIdx.x * blockDim.x + threadIdx.x;
    if (e < E) atomicAdd(&g_deg[dst[e]], 1);
}

// Scan stage 1: each CTA (256 thr) scans SCAN_CHUNK=1024 degrees locally.
// Writes block-local exclusive prefixes into g_rowptr and block sum to g_bsum.
__global__ void scan1_k(int n)
{
    const int tid  = threadIdx.x;
    const int blk  = blockIdx.x;
    const int base = blk * SCAN_CHUNK + tid * 4;

    int d0 = 0, d1 = 0, d2 = 0, d3 = 0;
    if (base     < n) d0 = g_deg[base];
    if (base + 1 < n) d1 = g_deg[base + 1];
    if (base + 2 < n) d2 = g_deg[base + 2];
    if (base + 3 < n) d3 = g_deg[base + 3];
    int s = d0 + d1 + d2 + d3;

    const int lane = tid & 31, wid = tid >> 5;
    int v = s;
#pragma unroll
    for (int off = 1; off < 32; off <<= 1) {
        int t = __shfl_up_sync(0xffffffffu, v, off);
        if (lane >= off) v += t;
    }
    __shared__ int ws[8];
    if (lane == 31) ws[wid] = v;
    __syncthreads();
    if (tid == 0) {
        int r = 0;
#pragma unroll
        for (int i = 0; i < 8; ++i) { int t = ws[i]; ws[i] = r; r += t; }
    }
    __syncthreads();

    int excl = (v - s) + ws[wid];
    if (tid == 255) g_bsum[blk] = excl + s;   // block total

    if (base     < n) g_rowptr[base]     = excl;           excl += d0;
    if (base + 1 < n) g_rowptr[base + 1] = excl;           excl += d1;
    if (base + 2 < n) g_rowptr[base + 2] = excl;           excl += d2;
    if (base + 3 < n) g_rowptr[base + 3] = excl;
}

// Scan stage 2: one warp exclusive-scans the <=64 block sums.
__global__ void scan2_k(int nb)
{
    const int lane = threadIdx.x;
    int i0 = lane * 2, i1 = lane * 2 + 1;
    int a = (i0 < nb) ? g_bsum[i0] : 0;
    int b = (i1 < nb) ? g_bsum[i1] : 0;
    int s = a + b, v = s;
#pragma unroll
    for (int off = 1; off < 32; off <<= 1) {
        int t = __shfl_up_sync(0xffffffffu, v, off);
        if (lane >= off) v += t;
    }
    int excl = v - s;
    if (i0 < nb) g_bsum[i0] = excl;
    if (i1 < nb) g_bsum[i1] = excl + a;
}

// Scan stage 3: add block offsets, materialize rowptr + cursor.
__global__ void scan3_k(int n, int E)
{
    const int tid  = threadIdx.x;
    const int blk  = blockIdx.x;
    const int off  = g_bsum[blk];
    const int base = blk * SCAN_CHUNK + tid * 4;
#pragma unroll
    for (int j = 0; j < 4; ++j) {
        int idx = base + j;
        if (idx < n) {
            int r = g_rowptr[idx] + off;
            g_rowptr[idx] = r;
            g_cursor[idx] = r;
        }
    }
    if (blk == 0 && tid == 0) g_rowptr[n] = E;
}

__global__ void scatter_k(const int* __restrict__ src, const int* __restrict__ dst,
                          const int* __restrict__ et, int E, int n)
{
    int e = blockIdx.x * blockDim.x + threadIdx.x;
    if (e >= E) return;
    int d   = dst[e];
    int pos = atomicAdd(&g_cursor[d], 1);
    g_elist[pos] = ((unsigned)et[e] * (unsigned)n + (unsigned)src[e]) * (unsigned)DFEAT;
}

// ---------------------------------------------------------------------------
// Pull: one warp per node. acc = feat[n] + sum over incoming edges of Y row.
// Unroll x4 for MLP against DRAM latency.
// ---------------------------------------------------------------------------
__global__ void __launch_bounds__(256)
pull_k(const float* __restrict__ feat, float* __restrict__ out, int n)
{
    int gw   = (blockIdx.x * 256 + threadIdx.x) >> 5;
    int lane = threadIdx.x & 31;
    if (gw >= n) return;

    int s = g_rowptr[gw];
    int e = g_rowptr[gw + 1];

    float4 acc = *((const float4*)feat + (size_t)gw * 32 + lane);

    int i = s;
    for (; i + 4 <= e; i += 4) {
        unsigned o0 = g_elist[i];
        unsigned o1 = g_elist[i + 1];
        unsigned o2 = g_elist[i + 2];
        unsigned o3 = g_elist[i + 3];
        float4 v0 = *(const float4*)(g_Y + (size_t)o0 + lane * 4);
        float4 v1 = *(const float4*)(g_Y + (size_t)o1 + lane * 4);
        float4 v2 = *(const float4*)(g_Y + (size_t)o2 + lane * 4);
        float4 v3 = *(const float4*)(g_Y + (size_t)o3 + lane * 4);
        acc.x += v0.x; acc.y += v0.y; acc.z += v0.z; acc.w += v0.w;
        acc.x += v1.x; acc.y += v1.y; acc.z += v1.z; acc.w += v1.w;
        acc.x += v2.x; acc.y += v2.y; acc.z += v2.z; acc.w += v2.w;
        acc.x += v3.x; acc.y += v3.y; acc.z += v3.z; acc.w += v3.w;
    }
    for (; i < e; ++i) {
        unsigned o = g_elist[i];
        float4 v = *(const float4*)(g_Y + (size_t)o + lane * 4);
        acc.x += v.x; acc.y += v.y; acc.z += v.z; acc.w += v.w;
    }

    *((float4*)out + (size_t)gw * 32 + lane) = acc;
}

// ---------------------------------------------------------------------------
// Launch
// ---------------------------------------------------------------------------
extern "C" void kernel_launch(void* const* d_in, const int* in_sizes, int n_in,
                              void* d_out, int out_size)
{
    const float* feat = (const float*)d_in[0];
    const float* W    = (const float*)d_in[1];
    const int*   et   = (const int*)d_in[2];
    const int*   src  = (const int*)d_in[3];
    const int*   dst  = (const int*)d_in[4];
    float*       out  = (float*)d_out;

    const int n = in_sizes[0] / DFEAT;                 // 50000
    const int R = in_sizes[1] / (DFEAT * DFEAT);       // 8
    const int E = in_sizes[2];                          // 640000
    const int nb = (n + SCAN_CHUNK - 1) / SCAN_CHUNK;  // 49

    const int smem_bytes = (TM * AS_LD + DFEAT * BS_LD) * 4;  // ~103 KB
    cudaFuncSetAttribute(gemm_feat_w,
                         cudaFuncAttributeMaxDynamicSharedMemorySize, smem_bytes);

    dim3 gg((n + TM - 1) / TM, R);
    gemm_feat_w<<<gg, 256, smem_bytes>>>(feat, W, n);

    zero_deg_k<<<(n + 255) / 256, 256>>>(n);
    hist_k<<<(E + 255) / 256, 256>>>(dst, E);
    scan1_k<<<nb, 256>>>(n);
    scan2_k<<<1, 32>>>(nb);
    scan3_k<<<nb, 256>>>(n, E);
    scatter_k<<<(E + 255) / 256, 256>>>(src, dst, et, E, n);

    pull_k<<<(n * 32 + 255) / 256, 256>>>(feat, out, n);
}